// round 14
// baseline (speedup 1.0000x reference)
#include <cuda_runtime.h>

// Problem constants
#define B_ 128
#define S_ 512
#define H_ 1024
#define NBLK 128

// ---------------- device scratch (no allocations allowed) ----------------
__device__ __align__(16) float g_p[B_ * H_];   // recurrent state p
__device__ __align__(16) float g_a[B_ * H_];   // a = r*p + x  (input to V GEMM)
__device__ __align__(16) float g_z[B_ * H_];   // z gate
__device__ __align__(16) float g_partA[8][16][128 * 128];  // A: 16 N-tiles, KS=8
__device__ __align__(16) float g_partB[16][8][128 * 128];  // B:  8 N-tiles, KS=16
__device__ unsigned g_bar_count;   // zero-initialized
__device__ unsigned g_bar_gen;

// ---------------- packed fp32x2 FMA (Blackwell, PTX-only) ----------------
__device__ __forceinline__ float2 ffma2(float2 a, float2 b, float2 c) {
    float2 d;
    asm("fma.rn.f32x2 %0, %1, %2, %3;"
        : "=l"(*reinterpret_cast<unsigned long long*>(&d))
        : "l"(*reinterpret_cast<unsigned long long*>(&a)),
          "l"(*reinterpret_cast<unsigned long long*>(&b)),
          "l"(*reinterpret_cast<unsigned long long*>(&c)));
    return d;
}

__device__ __forceinline__ float sigf(float x) { return 1.0f / (1.0f + __expf(-x)); }

// ---------------- grid-wide sense barrier (all 128 CTAs co-resident) ------
__device__ __forceinline__ void grid_bar() {
    __syncthreads();
    if (threadIdx.x == 0) {
        __threadfence();
        const unsigned gen = *((volatile unsigned*)&g_bar_gen);
        const unsigned old = atomicAdd(&g_bar_count, 1u);
        if (old == NBLK - 1) {
            atomicExch(&g_bar_count, 0u);
            __threadfence();
            atomicAdd(&g_bar_gen, 1u);
        } else {
            while (*((volatile unsigned*)&g_bar_gen) == gen) { __nanosleep(64); }
        }
        __threadfence();
    }
    __syncthreads();
}

// ==========================================================================
// Partial GEMM: CTA tile 128(M) x 128(N) over one K segment.
// PHASE 0: A = (emb[:,s,:]+p), W = [Ww|Uw]; PHASE 1: A = g_a, W = Vw.
// 256 threads, 8x8 outputs/thread, packed f32x2 accumulation.
// Cross-step data (g_p, g_a) read via __ldcg (L1 non-coherent in-launch);
// weights/emb via normal loads (L1-resident across steps).
// ==========================================================================
template <int PHASE>
__device__ __forceinline__ void gemm_partial(
    const int nt, const int ks, const int t, const int s,
    const float* __restrict__ emb,
    const float* __restrict__ Ww, const float* __restrict__ Uw,
    const float* __restrict__ Vw,
    float (&sA)[2][16][128], float (&sW)[2][16][128])
{
    constexpr int KS   = (PHASE == 0) ? 8 : 16;
    constexpr int KSEG = H_ / KS;      // 128 or 64
    constexpr int KC   = 16;
    constexpr int NC   = KSEG / KC;    // 8 or 4

    const int cg = t & 15;             // cols cg*8 .. cg*8+7
    const int rg = t >> 4;             // rows rg*8 .. rg*8+7

    const float* Wmat;
    int nbase;
    if (PHASE == 0) {
        if (nt < 8) { Wmat = Ww; nbase = nt * 128; }
        else        { Wmat = Uw; nbase = (nt - 8) * 128; }
    } else {
        Wmat = Vw; nbase = nt * 128;
    }
    const int k0 = ks * KSEG;
    const int lq = t >> 6;             // k-quad 0..3
    const int lm = t & 63;             // row/col 0..63 (+64 pass)

    float2 acc[8][4];
#pragma unroll
    for (int i = 0; i < 8; i++)
#pragma unroll
        for (int j = 0; j < 4; j++) acc[i][j] = make_float2(0.f, 0.f);

    float4 rA[2], rW[2];

    auto fetch = [&](int c) {
        const int kb = k0 + c * KC + lq * 4;
#pragma unroll
        for (int h = 0; h < 2; h++) {
            const int m = lm + h * 64;
            if (PHASE == 0) {
                const float4 e = *(const float4*)(emb + (size_t)m * S_ * H_ + (size_t)s * H_ + kb);
                const float4 p = __ldcg((const float4*)(g_p + m * H_ + kb));
                rA[h] = make_float4(e.x + p.x, e.y + p.y, e.z + p.z, e.w + p.w);
            } else {
                rA[h] = __ldcg((const float4*)(g_a + m * H_ + kb));
            }
            rW[h] = *(const float4*)(Wmat + (size_t)(nbase + m) * H_ + kb);
        }
    };

    auto store_smem = [&](int buf) {
        const int kk = lq * 4;
#pragma unroll
        for (int h = 0; h < 2; h++) {
            const int m = lm + h * 64;
            sA[buf][kk + 0][m] = rA[h].x;  sA[buf][kk + 1][m] = rA[h].y;
            sA[buf][kk + 2][m] = rA[h].z;  sA[buf][kk + 3][m] = rA[h].w;
            sW[buf][kk + 0][m] = rW[h].x;  sW[buf][kk + 1][m] = rW[h].y;
            sW[buf][kk + 2][m] = rW[h].z;  sW[buf][kk + 3][m] = rW[h].w;
        }
    };

    auto compute = [&](int buf) {
#pragma unroll
        for (int kk = 0; kk < KC; kk++) {
            const float4 a0 = *(const float4*)&sA[buf][kk][rg * 8];
            const float4 a1 = *(const float4*)&sA[buf][kk][rg * 8 + 4];
            const float4 w0 = *(const float4*)&sW[buf][kk][cg * 8];
            const float4 w1 = *(const float4*)&sW[buf][kk][cg * 8 + 4];
            float  a[8] = {a0.x, a0.y, a0.z, a0.w, a1.x, a1.y, a1.z, a1.w};
            float2 b[4] = {make_float2(w0.x, w0.y), make_float2(w0.z, w0.w),
                           make_float2(w1.x, w1.y), make_float2(w1.z, w1.w)};
#pragma unroll
            for (int i = 0; i < 8; i++) {
                const float2 ai = make_float2(a[i], a[i]);
#pragma unroll
                for (int j = 0; j < 4; j++)
                    acc[i][j] = ffma2(ai, b[j], acc[i][j]);
            }
        }
    };

    fetch(0);
    store_smem(0);
#pragma unroll 1
    for (int c = 0; c < NC; c++) {
        __syncthreads();
        if (c + 1 < NC) fetch(c + 1);
        compute(c & 1);
        if (c + 1 < NC) store_smem((c + 1) & 1);
    }

    float* part = (PHASE == 0) ? g_partA[ks][nt] : g_partB[ks][nt];
    const int r0 = rg * 8, c0 = cg * 8;
#pragma unroll
    for (int i = 0; i < 8; i++) {
        __stcg((float4*)(part + (r0 + i) * 128 + c0),
               make_float4(acc[i][0].x, acc[i][0].y, acc[i][1].x, acc[i][1].y));
        __stcg((float4*)(part + (r0 + i) * 128 + c0 + 4),
               make_float4(acc[i][2].x, acc[i][2].y, acc[i][3].x, acc[i][3].y));
    }
}

// ---- reduce A: sum 8 K-partials, gate epilogue -> g_a (r) / g_z (z) ------
__device__ __forceinline__ void reduceA(
    const int r, const int t, const int s,
    const float* __restrict__ emb,
    const float* __restrict__ Wb, const float* __restrict__ Ub)
{
    const int nt = r >> 3;              // 0..15
    const int rb = (r & 7) * 16;        // 16 rows per CTA
    const int ri = t >> 5;              // 0..7
    const int col = (t & 31) * 4;       // 0..124
    const int nbase = (nt < 8) ? nt * 128 : (nt - 8) * 128;
    const int hc = nbase + col;
#pragma unroll
    for (int it = 0; it < 2; it++) {
        const int m = rb + it * 8 + ri;
        float4 sum = make_float4(0.f, 0.f, 0.f, 0.f);
#pragma unroll
        for (int kss = 0; kss < 8; kss++) {
            const float4 u = __ldcg((const float4*)(g_partA[kss][nt] + m * 128 + col));
            sum.x += u.x; sum.y += u.y; sum.z += u.z; sum.w += u.w;
        }
        if (nt < 8) {                   // r gate: g_a = sigmoid(.)*p + x
            const float4 b = *(const float4*)(Wb + hc);
            const float4 x = *(const float4*)(emb + (size_t)m * S_ * H_ + (size_t)s * H_ + hc);
            const float4 p = __ldcg((const float4*)(g_p + m * H_ + hc));
            float4 a;
            a.x = fmaf(sigf(sum.x + b.x), p.x, x.x);
            a.y = fmaf(sigf(sum.y + b.y), p.y, x.y);
            a.z = fmaf(sigf(sum.z + b.z), p.z, x.z);
            a.w = fmaf(sigf(sum.w + b.w), p.w, x.w);
            __stcg((float4*)(g_a + m * H_ + hc), a);
        } else {                        // z gate
            const float4 b = *(const float4*)(Ub + hc);
            float4 zv;
            zv.x = sigf(sum.x + b.x);  zv.y = sigf(sum.y + b.y);
            zv.z = sigf(sum.z + b.z);  zv.w = sigf(sum.w + b.w);
            __stcg((float4*)(g_z + m * H_ + hc), zv);
        }
    }
}

// ---- reduce B: sum 16 K-partials, h=tanh, state update -> g_p, out -------
__device__ __forceinline__ void reduceB(
    const int r, const int t, const int s,
    const float* __restrict__ Vb, float* __restrict__ out)
{
    const int nt = r >> 4;              // 0..7
    const int rb = (r & 15) * 8;        // 8 rows per CTA
    const int m  = rb + (t >> 5);
    const int col = (t & 31) * 4;
    const int hc = nt * 128 + col;

    float4 sum = make_float4(0.f, 0.f, 0.f, 0.f);
#pragma unroll
    for (int kss = 0; kss < 16; kss++) {
        const float4 u = __ldcg((const float4*)(g_partB[kss][nt] + m * 128 + col));
        sum.x += u.x; sum.y += u.y; sum.z += u.z; sum.w += u.w;
    }
    const float4 b  = *(const float4*)(Vb + hc);
    const float4 zv = __ldcg((const float4*)(g_z + m * H_ + hc));
    const float4 pv = __ldcg((const float4*)(g_p + m * H_ + hc));
    float4 pn;
    pn.x = fmaf(zv.x, tanhf(sum.x + b.x) - pv.x, pv.x);
    pn.y = fmaf(zv.y, tanhf(sum.y + b.y) - pv.y, pv.y);
    pn.z = fmaf(zv.z, tanhf(sum.z + b.z) - pv.z, pv.z);
    pn.w = fmaf(zv.w, tanhf(sum.w + b.w) - pv.w, pv.w);
    __stcg((float4*)(g_p + m * H_ + hc), pn);
    *(float4*)(out + (size_t)m * S_ * H_ + (size_t)s * H_ + hc) = pn;
}

// ==========================================================================
// Persistent kernel: whole 512-step scan in ONE launch (1 graph node).
// 128 CTAs x 256 thr — all co-resident on 148 SMs; 4 grid barriers/step.
// ==========================================================================
__global__ void __launch_bounds__(256) gru_persistent(
    const float* __restrict__ emb,
    const float* __restrict__ Ww, const float* __restrict__ Wb,
    const float* __restrict__ Uw, const float* __restrict__ Ub,
    const float* __restrict__ Vw, const float* __restrict__ Vb,
    float* __restrict__ out)
{
    __shared__ float sA[2][16][128];
    __shared__ float sW[2][16][128];

    const int r = blockIdx.x;
    const int t = threadIdx.x;

    // init p = 0 (each CTA zeros its 1024-float slice)
    __stcg((float4*)(g_p + r * 1024 + t * 4), make_float4(0.f, 0.f, 0.f, 0.f));
    grid_bar();

#pragma unroll 1
    for (int s = 0; s < S_; s++) {
        gemm_partial<0>(r & 15, r >> 4, t, s, emb, Ww, Uw, Vw, sA, sW);
        grid_bar();
        reduceA(r, t, s, emb, Wb, Ub);
        grid_bar();
        gemm_partial<1>(r & 7, r >> 3, t, s, emb, Ww, Uw, Vw, sA, sW);
        grid_bar();
        reduceB(r, t, s, Vb, out);
        grid_bar();
    }
}

extern "C" void kernel_launch(void* const* d_in, const int* in_sizes, int n_in,
                              void* d_out, int out_size) {
    const float* emb = (const float*)d_in[0];
    const float* Ww  = (const float*)d_in[1];
    const float* Wb  = (const float*)d_in[2];
    const float* Uw  = (const float*)d_in[3];
    const float* Ub  = (const float*)d_in[4];
    const float* Vw  = (const float*)d_in[5];
    const float* Vb  = (const float*)d_in[6];
    float* out = (float*)d_out;

    gru_persistent<<<NBLK, 256>>>(emb, Ww, Wb, Uw, Ub, Vw, Vb, out);
}

// round 17
// speedup vs baseline: 1.1311x; 1.1311x over previous
#include <cuda_runtime.h>

// Problem constants
#define B_ 128
#define S_ 512
#define H_ 1024
#define NBLK 128

// ---------------- device scratch (no allocations allowed) ----------------
__device__ __align__(16) float g_p[B_ * H_];   // recurrent state p
__device__ __align__(16) float g_a[B_ * H_];   // a = r*p + x  (input to V GEMM)
__device__ __align__(16) float g_z[B_ * H_];   // z gate
__device__ __align__(16) float g_partA[8][16][128 * 128];  // A: 16 N-tiles, KS=8
__device__ __align__(16) float g_partB[16][8][128 * 128];  // B:  8 N-tiles, KS=16
__device__ unsigned g_bar_count;   // zero-initialized
__device__ unsigned g_bar_gen;

// ---------------- packed fp32x2 FMA (Blackwell, PTX-only) ----------------
__device__ __forceinline__ float2 ffma2(float2 a, float2 b, float2 c) {
    float2 d;
    asm("fma.rn.f32x2 %0, %1, %2, %3;"
        : "=l"(*reinterpret_cast<unsigned long long*>(&d))
        : "l"(*reinterpret_cast<unsigned long long*>(&a)),
          "l"(*reinterpret_cast<unsigned long long*>(&b)),
          "l"(*reinterpret_cast<unsigned long long*>(&c)));
    return d;
}

__device__ __forceinline__ float sigf(float x) { return 1.0f / (1.0f + __expf(-x)); }

// ---------------- grid-wide sense barrier (all 128 CTAs co-resident) ------
__device__ __forceinline__ void grid_bar() {
    __syncthreads();
    if (threadIdx.x == 0) {
        __threadfence();
        const unsigned gen = *((volatile unsigned*)&g_bar_gen);
        const unsigned old = atomicAdd(&g_bar_count, 1u);
        if (old == NBLK - 1) {
            atomicExch(&g_bar_count, 0u);
            __threadfence();
            atomicAdd(&g_bar_gen, 1u);
        } else {
            while (*((volatile unsigned*)&g_bar_gen) == gen) { __nanosleep(64); }
        }
        __threadfence();
    }
    __syncthreads();
}

// ==========================================================================
// Partial GEMM: CTA tile 128(M) x 128(N) over one K segment.
// 512 threads, 8x4 outputs/thread (acc = 16 float2), register fragment
// double-buffering to hide the 29-cyc LDS latency within each warp.
// PHASE 0: A = (emb[:,s,:]+p), W = [Ww|Uw]; PHASE 1: A = g_a, W = Vw.
// Cross-step data (g_p, g_a, partials) via __ldcg/__stcg (L2-coherent);
// weights/emb via normal loads (L1-resident across steps).
// ==========================================================================
template <int PHASE>
__device__ __forceinline__ void gemm_partial(
    const int nt, const int ks, const int t, const int s,
    const float* __restrict__ emb,
    const float* __restrict__ Ww, const float* __restrict__ Uw,
    const float* __restrict__ Vw,
    float (&sA)[2][16][128], float (&sW)[2][16][128])
{
    constexpr int KS   = (PHASE == 0) ? 8 : 16;
    constexpr int KSEG = H_ / KS;      // 128 or 64
    constexpr int KC   = 16;
    constexpr int NC   = KSEG / KC;    // 8 or 4

    const int cg = t & 31;             // cols cg*4 .. cg*4+3
    const int rg = (t >> 5) & 15;      // rows rg*8 .. rg*8+7

    const float* Wmat;
    int nbase;
    if (PHASE == 0) {
        if (nt < 8) { Wmat = Ww; nbase = nt * 128; }
        else        { Wmat = Uw; nbase = (nt - 8) * 128; }
    } else {
        Wmat = Vw; nbase = nt * 128;
    }
    const int k0 = ks * KSEG;
    const int lm = t & 127;            // loader row/col 0..127
    const int lq = t >> 7;             // loader k-quad 0..3

    float2 acc[8][2];
#pragma unroll
    for (int i = 0; i < 8; i++) { acc[i][0] = make_float2(0.f, 0.f); acc[i][1] = make_float2(0.f, 0.f); }

    float4 rA, rW;

    auto fetch = [&](int c) {
        const int kb = k0 + c * KC + lq * 4;
        if (PHASE == 0) {
            const float4 e = *(const float4*)(emb + (size_t)lm * S_ * H_ + (size_t)s * H_ + kb);
            const float4 p = __ldcg((const float4*)(g_p + lm * H_ + kb));
            rA = make_float4(e.x + p.x, e.y + p.y, e.z + p.z, e.w + p.w);
        } else {
            rA = __ldcg((const float4*)(g_a + lm * H_ + kb));
        }
        rW = *(const float4*)(Wmat + (size_t)(nbase + lm) * H_ + kb);
    };

    auto store_smem = [&](int buf) {
        const int kk = lq * 4;
        sA[buf][kk + 0][lm] = rA.x;  sA[buf][kk + 1][lm] = rA.y;
        sA[buf][kk + 2][lm] = rA.z;  sA[buf][kk + 3][lm] = rA.w;
        sW[buf][kk + 0][lm] = rW.x;  sW[buf][kk + 1][lm] = rW.y;
        sW[buf][kk + 2][lm] = rW.z;  sW[buf][kk + 3][lm] = rW.w;
    };

    auto compute = [&](int buf) {
        float4 fa0[2], fa1[2], fw[2];
        // preload fragment for kk = 0
        fa0[0] = *(const float4*)&sA[buf][0][rg * 8];
        fa1[0] = *(const float4*)&sA[buf][0][rg * 8 + 4];
        fw[0]  = *(const float4*)&sW[buf][0][cg * 4];
#pragma unroll
        for (int kk = 0; kk < KC; kk++) {
            const int cur = kk & 1;
            if (kk + 1 < KC) {            // prefetch next fragment (hides LDS lat)
                const int nxt = (kk + 1) & 1;
                fa0[nxt] = *(const float4*)&sA[buf][kk + 1][rg * 8];
                fa1[nxt] = *(const float4*)&sA[buf][kk + 1][rg * 8 + 4];
                fw[nxt]  = *(const float4*)&sW[buf][kk + 1][cg * 4];
            }
            const float a[8] = {fa0[cur].x, fa0[cur].y, fa0[cur].z, fa0[cur].w,
                                fa1[cur].x, fa1[cur].y, fa1[cur].z, fa1[cur].w};
            const float2 w0 = make_float2(fw[cur].x, fw[cur].y);
            const float2 w1 = make_float2(fw[cur].z, fw[cur].w);
#pragma unroll
            for (int i = 0; i < 8; i++) {
                const float2 ai = make_float2(a[i], a[i]);
                acc[i][0] = ffma2(ai, w0, acc[i][0]);
                acc[i][1] = ffma2(ai, w1, acc[i][1]);
            }
        }
    };

    fetch(0);
    store_smem(0);
#pragma unroll 1
    for (int c = 0; c < NC; c++) {
        __syncthreads();
        if (c + 1 < NC) fetch(c + 1);
        compute(c & 1);
        if (c + 1 < NC) store_smem((c + 1) & 1);
    }

    float* part = (PHASE == 0) ? g_partA[ks][nt] : g_partB[ks][nt];
    const int r0 = rg * 8, c0 = cg * 4;
#pragma unroll
    for (int i = 0; i < 8; i++) {
        __stcg((float4*)(part + (r0 + i) * 128 + c0),
               make_float4(acc[i][0].x, acc[i][0].y, acc[i][1].x, acc[i][1].y));
    }
}

// ---- reduce A: sum 8 K-partials, gate epilogue -> g_a (r) / g_z (z) ------
// 512 threads: exactly one float4 per thread (16 rows x 128 cols per CTA).
__device__ __forceinline__ void reduceA(
    const int r, const int t, const int s,
    const float* __restrict__ emb,
    const float* __restrict__ Wb, const float* __restrict__ Ub)
{
    const int nt = r >> 3;              // 0..15
    const int rb = (r & 7) * 16;        // 16 rows per CTA
    const int m  = rb + (t >> 5);       // 16 rows
    const int col = (t & 31) * 4;       // 0..124
    const int nbase = (nt < 8) ? nt * 128 : (nt - 8) * 128;
    const int hc = nbase + col;

    float4 sum = make_float4(0.f, 0.f, 0.f, 0.f);
#pragma unroll
    for (int kss = 0; kss < 8; kss++) {
        const float4 u = __ldcg((const float4*)(g_partA[kss][nt] + m * 128 + col));
        sum.x += u.x; sum.y += u.y; sum.z += u.z; sum.w += u.w;
    }
    if (nt < 8) {                       // r gate: g_a = sigmoid(.)*p + x
        const float4 b = *(const float4*)(Wb + hc);
        const float4 x = *(const float4*)(emb + (size_t)m * S_ * H_ + (size_t)s * H_ + hc);
        const float4 p = __ldcg((const float4*)(g_p + m * H_ + hc));
        float4 a;
        a.x = fmaf(sigf(sum.x + b.x), p.x, x.x);
        a.y = fmaf(sigf(sum.y + b.y), p.y, x.y);
        a.z = fmaf(sigf(sum.z + b.z), p.z, x.z);
        a.w = fmaf(sigf(sum.w + b.w), p.w, x.w);
        __stcg((float4*)(g_a + m * H_ + hc), a);
    } else {                            // z gate
        const float4 b = *(const float4*)(Ub + hc);
        float4 zv;
        zv.x = sigf(sum.x + b.x);  zv.y = sigf(sum.y + b.y);
        zv.z = sigf(sum.z + b.z);  zv.w = sigf(sum.w + b.w);
        __stcg((float4*)(g_z + m * H_ + hc), zv);
    }
}

// ---- reduce B: sum 16 K-partials, h=tanh, state update -> g_p, out -------
// 512 threads, first 256 active (8 rows x 128 cols per CTA).
__device__ __forceinline__ void reduceB(
    const int r, const int t, const int s,
    const float* __restrict__ Vb, float* __restrict__ out)
{
    if (t >= 256) return;
    const int nt = r >> 4;              // 0..7
    const int rb = (r & 15) * 8;        // 8 rows per CTA
    const int m  = rb + (t >> 5);
    const int col = (t & 31) * 4;
    const int hc = nt * 128 + col;

    float4 sum = make_float4(0.f, 0.f, 0.f, 0.f);
#pragma unroll
    for (int kss = 0; kss < 16; kss++) {
        const float4 u = __ldcg((const float4*)(g_partB[kss][nt] + m * 128 + col));
        sum.x += u.x; sum.y += u.y; sum.z += u.z; sum.w += u.w;
    }
    const float4 b  = *(const float4*)(Vb + hc);
    const float4 zv = __ldcg((const float4*)(g_z + m * H_ + hc));
    const float4 pv = __ldcg((const float4*)(g_p + m * H_ + hc));
    float4 pn;
    pn.x = fmaf(zv.x, tanhf(sum.x + b.x) - pv.x, pv.x);
    pn.y = fmaf(zv.y, tanhf(sum.y + b.y) - pv.y, pv.y);
    pn.z = fmaf(zv.z, tanhf(sum.z + b.z) - pv.z, pv.z);
    pn.w = fmaf(zv.w, tanhf(sum.w + b.w) - pv.w, pv.w);
    __stcg((float4*)(g_p + m * H_ + hc), pn);
    *(float4*)(out + (size_t)m * S_ * H_ + (size_t)s * H_ + hc) = pn;
}

// ==========================================================================
// Persistent kernel: whole 512-step scan in ONE launch (1 graph node).
// 128 CTAs x 512 thr (16 warps = 4/SMSP) — co-resident; 4 grid barriers/step.
// ==========================================================================
__global__ void __launch_bounds__(512) gru_persistent(
    const float* __restrict__ emb,
    const float* __restrict__ Ww, const float* __restrict__ Wb,
    const float* __restrict__ Uw, const float* __restrict__ Ub,
    const float* __restrict__ Vw, const float* __restrict__ Vb,
    float* __restrict__ out)
{
    __shared__ float sA[2][16][128];
    __shared__ float sW[2][16][128];

    const int r = blockIdx.x;
    const int t = threadIdx.x;

    // init p = 0 (each CTA zeros its 1024-float slice; 512 thr x float2)
    __stcg((float2*)(g_p + r * 1024 + t * 2), make_float2(0.f, 0.f));
    grid_bar();

#pragma unroll 1
    for (int s = 0; s < S_; s++) {
        gemm_partial<0>(r & 15, r >> 4, t, s, emb, Ww, Uw, Vw, sA, sW);
        grid_bar();
        reduceA(r, t, s, emb, Wb, Ub);
        grid_bar();
        gemm_partial<1>(r & 7, r >> 3, t, s, emb, Ww, Uw, Vw, sA, sW);
        grid_bar();
        reduceB(r, t, s, Vb, out);
        grid_bar();
    }
}

extern "C" void kernel_launch(void* const* d_in, const int* in_sizes, int n_in,
                              void* d_out, int out_size) {
    const float* emb = (const float*)d_in[0];
    const float* Ww  = (const float*)d_in[1];
    const float* Wb  = (const float*)d_in[2];
    const float* Uw  = (const float*)d_in[3];
    const float* Ub  = (const float*)d_in[4];
    const float* Vw  = (const float*)d_in[5];
    const float* Vb  = (const float*)d_in[6];
    float* out = (float*)d_out;

    gru_persistent<<<NBLK, 512>>>(emb, Ww, Wb, Uw, Ub, Vw, Vb, out);
}